// round 5
// baseline (speedup 1.0000x reference)
#include <cuda_runtime.h>
#include <math.h>

// Problem constants (B=4, S=4096, D=768)
#define D_HALF 768
#define V_HALF 192            // float4s per half-row
#define NT 192                // one float4 column per thread
#define NW 6                  // warps per block
#define ROWS_PER_BLOCK 4
#define LN_EPS 1e-5f
#define INV_N (1.0f / 1536.0f)

__device__ __forceinline__ float4 ldcs4(const float4* p) {
    float4 v;
    asm volatile("ld.global.cs.v4.f32 {%0,%1,%2,%3}, [%4];"
                 : "=f"(v.x), "=f"(v.y), "=f"(v.z), "=f"(v.w) : "l"(p));
    return v;
}
__device__ __forceinline__ void stcs4(float4* p, float4 v) {
    asm volatile("st.global.cs.v4.f32 [%0], {%1,%2,%3,%4};"
                 :: "l"(p), "f"(v.x), "f"(v.y), "f"(v.z), "f"(v.w));
}

__device__ __forceinline__ float hsum4(float4 v) { return (v.x + v.y) + (v.z + v.w); }
__device__ __forceinline__ float dot4(float4 a, float4 b) {
    return a.x*b.x + a.y*b.y + a.z*b.z + a.w*b.w;
}
__device__ __forceinline__ float4 mul4(float4 a, float4 b) {
    return make_float4(a.x*b.x, a.y*b.y, a.z*b.z, a.w*b.w);
}

// Reduce 5 float4 vectors across a warp simultaneously (ILP hides SHFL latency).
__device__ __forceinline__ void warp_reduce4x5(float4* v) {
#pragma unroll
    for (int o = 16; o > 0; o >>= 1) {
#pragma unroll
        for (int k = 0; k < 5; k++) {
            v[k].x += __shfl_down_sync(0xffffffffu, v[k].x, o);
            v[k].y += __shfl_down_sync(0xffffffffu, v[k].y, o);
            v[k].z += __shfl_down_sync(0xffffffffu, v[k].z, o);
            v[k].w += __shfl_down_sync(0xffffffffu, v[k].w, o);
        }
    }
}

// ---------------------------------------------------------------------------
// Single fused kernel, single wave, 4 rows/block.
// Per-block constants ride the same reduction tree as the row accumulators.
// ---------------------------------------------------------------------------
__global__ __launch_bounds__(NT)
void attention_fusion_kernel(const float4* __restrict__ seq,
                             const float4* __restrict__ msa,
                             const float4* __restrict__ gamma,
                             const float4* __restrict__ beta,
                             const float4* __restrict__ gate_w,
                             const float*  __restrict__ gate_b,
                             float4* __restrict__ out) {
    __shared__ float4 sh_row[ROWS_PER_BLOCK][NW];
    __shared__ float4 sh_c[NW];
    __shared__ float  sh_w0[ROWS_PER_BLOCK];

    const int t = threadIdx.x;     // 0..191
    const int wid = t >> 5, lid = t & 31;

    // ---- all loads issued up front (params .ca = L1-resident; data .cs) ----
    const float4 gs  = __ldg(gamma  + t);
    const float4 gm  = __ldg(gamma  + V_HALF + t);
    const float4 w0s = __ldg(gate_w + t);
    const float4 w0m = __ldg(gate_w + V_HALF + t);
    const float4 w1s = __ldg(gate_w + 2 * V_HALF + t);
    const float4 w1m = __ldg(gate_w + 3 * V_HALF + t);
    const float4 bs  = __ldg(beta   + t);
    const float4 bm  = __ldg(beta   + V_HALF + t);

    const long long base = (long long)blockIdx.x * ROWS_PER_BLOCK;
    const float4* sp = seq + base * V_HALF + t;
    const float4* mp = msa + base * V_HALF + t;
    float4*       op = out + base * V_HALF + t;

    float4 s[ROWS_PER_BLOCK], m[ROWS_PER_BLOCK];
#pragma unroll
    for (int r = 0; r < ROWS_PER_BLOCK; r++) {
        s[r] = ldcs4(sp + r * V_HALF);
        m[r] = ldcs4(mp + r * V_HALF);
    }

    // ---- per-thread param partials (overwrite w regs with q products) ----
    const float4 q0s = mul4(gs, w0s);
    const float4 q0m = mul4(gm, w0m);
    const float4 q1s = mul4(gs, w1s);
    const float4 q1m = mul4(gm, w1m);

    // acc[0..3] = per-row {sum, sumsq, dot0, dot1}; acc[4] = const partial
    float4 acc[5];
#pragma unroll
    for (int r = 0; r < ROWS_PER_BLOCK; r++) {
        float4 sv = s[r], mv = m[r];
        float4 a;
        a.x = hsum4(sv) + hsum4(mv);
        a.y = dot4(sv, sv) + dot4(mv, mv);
        a.z = dot4(sv, q0s) + dot4(mv, q0m);
        a.w = dot4(sv, q1s) + dot4(mv, q1m);
        acc[r] = a;
    }
    acc[4].x = hsum4(q0s) + hsum4(q0m);          // sum(gamma*w0)
    acc[4].y = hsum4(q1s) + hsum4(q1m);          // sum(gamma*w1)
    acc[4].z = dot4(bs, w0s) + dot4(bm, w0m);    // sum(beta*w0)
    acc[4].w = dot4(bs, w1s) + dot4(bm, w1m);    // sum(beta*w1)

    warp_reduce4x5(acc);
    if (lid == 0) {
#pragma unroll
        for (int r = 0; r < ROWS_PER_BLOCK; r++) sh_row[r][wid] = acc[r];
        sh_c[wid] = acc[4];
    }
    __syncthreads();

    // Warps 0..3 each finalize one row (and redundantly reduce the const).
    if (wid < ROWS_PER_BLOCK) {
        float4 a = (lid < NW) ? sh_row[wid][lid] : make_float4(0.f, 0.f, 0.f, 0.f);
        float4 c = (lid < NW) ? sh_c[lid]        : make_float4(0.f, 0.f, 0.f, 0.f);
#pragma unroll
        for (int o = 4; o > 0; o >>= 1) {
            a.x += __shfl_down_sync(0xffffffffu, a.x, o);
            a.y += __shfl_down_sync(0xffffffffu, a.y, o);
            a.z += __shfl_down_sync(0xffffffffu, a.z, o);
            a.w += __shfl_down_sync(0xffffffffu, a.w, o);
            c.x += __shfl_down_sync(0xffffffffu, c.x, o);
            c.y += __shfl_down_sync(0xffffffffu, c.y, o);
            c.z += __shfl_down_sync(0xffffffffu, c.z, o);
            c.w += __shfl_down_sync(0xffffffffu, c.w, o);
        }
        if (lid == 0) {
            float mean = a.x * INV_N;
            float var  = fmaf(-mean, mean, a.y * INV_N);
            float rstd = rsqrtf(var + LN_EPS);
            float l0 = fmaf(rstd, a.z - mean * c.x, c.z + __ldg(gate_b + 0));
            float l1 = fmaf(rstd, a.w - mean * c.y, c.w + __ldg(gate_b + 1));
            sh_w0[wid] = 1.0f / (1.0f + __expf(l1 - l0));
        }
    }
    __syncthreads();

#pragma unroll
    for (int r = 0; r < ROWS_PER_BLOCK; r++) {
        float w0 = sh_w0[r];
        float w1 = 1.0f - w0;
        float4 o;
        o.x = fmaf(w0, s[r].x, w1 * m[r].x);
        o.y = fmaf(w0, s[r].y, w1 * m[r].y);
        o.z = fmaf(w0, s[r].z, w1 * m[r].z);
        o.w = fmaf(w0, s[r].w, w1 * m[r].w);
        stcs4(op + r * V_HALF, o);
    }
}

// ---------------------------------------------------------------------------
// Launch: single kernel, single graph node.
// ---------------------------------------------------------------------------
extern "C" void kernel_launch(void* const* d_in, const int* in_sizes, int n_in,
                              void* d_out, int out_size) {
    const float* seq    = (const float*)d_in[0];
    const float* msa    = (const float*)d_in[1];
    const float* gamma  = (const float*)d_in[2];
    const float* beta   = (const float*)d_in[3];
    const float* gate_w = (const float*)d_in[4];
    const float* gate_b = (const float*)d_in[5];
    float* out = (float*)d_out;

    int rows   = in_sizes[0] / D_HALF;          // B*S = 16384
    int blocks = rows / ROWS_PER_BLOCK;         // 4096

    attention_fusion_kernel<<<blocks, NT>>>((const float4*)seq,
                                            (const float4*)msa,
                                            (const float4*)gamma,
                                            (const float4*)beta,
                                            (const float4*)gate_w,
                                            gate_b,
                                            (float4*)out);
}

// round 6
// speedup vs baseline: 1.4216x; 1.4216x over previous
#include <cuda_runtime.h>
#include <math.h>

// Problem constants (B=4, S=4096, D=768)
#define D_HALF 768
#define D_FULL 1536
#define V_HALF 192            // 768 / 4 float4s per half-row
#define NT_MAIN 192           // one float4 column per thread
#define NWARPS_MAIN 6
#define ROWS_PER_BLOCK 4
#define NT_PRE 256
#define LN_EPS 1e-5f

// Row-independent constants:
// [0] = sum(gamma*w0)   [1] = sum(gamma*w1)
// [2] = sum(beta*w0)+b0 [3] = sum(beta*w1)+b1
__device__ float  g_row_const[4];
// Precomputed products: gw0[j]=gamma[j]*w0[j], gw1[j]=gamma[j]*w1[j]
__device__ __align__(16) float g_gw0[D_FULL];
__device__ __align__(16) float g_gw1[D_FULL];

__device__ __forceinline__ float4 ldcs4(const float4* p) {
    float4 v;
    asm volatile("ld.global.cs.v4.f32 {%0,%1,%2,%3}, [%4];"
                 : "=f"(v.x), "=f"(v.y), "=f"(v.z), "=f"(v.w) : "l"(p));
    return v;
}
__device__ __forceinline__ void stcs4(float4* p, float4 v) {
    asm volatile("st.global.cs.v4.f32 [%0], {%1,%2,%3,%4};"
                 :: "l"(p), "f"(v.x), "f"(v.y), "f"(v.z), "f"(v.w));
}

__device__ __forceinline__ float4 warp_reduce4(float4 v) {
#pragma unroll
    for (int o = 16; o > 0; o >>= 1) {
        v.x += __shfl_down_sync(0xffffffffu, v.x, o);
        v.y += __shfl_down_sync(0xffffffffu, v.y, o);
        v.z += __shfl_down_sync(0xffffffffu, v.z, o);
        v.w += __shfl_down_sync(0xffffffffu, v.w, o);
    }
    return v;
}

// ---------------------------------------------------------------------------
// Prologue: row-independent constants + gamma*w product table. One block.
// ---------------------------------------------------------------------------
__global__ void gate_const_kernel(const float* __restrict__ gamma,
                                  const float* __restrict__ beta,
                                  const float* __restrict__ gate_w,
                                  const float* __restrict__ gate_b) {
    __shared__ float4 sh[NT_PRE / 32];
    float4 acc = make_float4(0.f, 0.f, 0.f, 0.f);
    for (int j = threadIdx.x; j < D_FULL; j += NT_PRE) {
        float g  = gamma[j];
        float be = beta[j];
        float w0 = gate_w[j];
        float w1 = gate_w[D_FULL + j];
        g_gw0[j] = g * w0;
        g_gw1[j] = g * w1;
        acc.x += g  * w0;
        acc.y += g  * w1;
        acc.z += be * w0;
        acc.w += be * w1;
    }
    acc = warp_reduce4(acc);
    int wid = threadIdx.x >> 5, lid = threadIdx.x & 31;
    if (lid == 0) sh[wid] = acc;
    __syncthreads();
    if (wid == 0) {
        acc = (lid < NT_PRE / 32) ? sh[lid] : make_float4(0.f, 0.f, 0.f, 0.f);
        acc = warp_reduce4(acc);
        if (lid == 0) {
            g_row_const[0] = acc.x;
            g_row_const[1] = acc.y;
            g_row_const[2] = acc.z + gate_b[0];
            g_row_const[3] = acc.w + gate_b[1];
        }
    }
#if __CUDA_ARCH__ >= 900
    cudaTriggerProgrammaticLaunchCompletion();
#endif
}

// ---------------------------------------------------------------------------
// Main fused kernel (R3 core): 192 threads, 4 rows per block.
// PDL: issue independent data loads first, then wait for the prologue grid,
// then read the gw table.
// ---------------------------------------------------------------------------
__global__ __launch_bounds__(NT_MAIN)
void attention_fusion_kernel(const float4* __restrict__ seq,
                             const float4* __restrict__ msa,
                             float4* __restrict__ out) {
    __shared__ float4 sh[ROWS_PER_BLOCK][NWARPS_MAIN];
    __shared__ float sh_w0[ROWS_PER_BLOCK];

    const int t = threadIdx.x;                 // 0..191
    const long long base = (long long)blockIdx.x * ROWS_PER_BLOCK;
    const float4* sp = seq + base * V_HALF + t;
    const float4* mp = msa + base * V_HALF + t;
    float4*       op = out + base * V_HALF + t;

    // Independent of the prologue: batch all data loads (MLP = 8 LDG.128)
    float4 s[ROWS_PER_BLOCK], m[ROWS_PER_BLOCK];
#pragma unroll
    for (int r = 0; r < ROWS_PER_BLOCK; r++) {
        s[r] = ldcs4(sp + r * V_HALF);
        m[r] = ldcs4(mp + r * V_HALF);
    }

    // Wait for the prologue grid's memory to be visible, then read the table.
#if __CUDA_ARCH__ >= 900
    cudaGridDependencySynchronize();
#endif

    const float4* gw0v = (const float4*)g_gw0;
    const float4* gw1v = (const float4*)g_gw1;
    const float4 g0s = gw0v[t];
    const float4 g0m = gw0v[V_HALF + t];
    const float4 g1s = gw1v[t];
    const float4 g1m = gw1v[V_HALF + t];

    // Per-row accumulators: x=sum, y=sumsq, z=dot0, w=dot1
    float4 acc[ROWS_PER_BLOCK];
#pragma unroll
    for (int r = 0; r < ROWS_PER_BLOCK; r++) {
        float4 sv = s[r], mv = m[r];
        float4 a;
        a.x = (sv.x + sv.y + sv.z + sv.w) + (mv.x + mv.y + mv.z + mv.w);
        a.y = sv.x*sv.x + sv.y*sv.y + sv.z*sv.z + sv.w*sv.w
            + mv.x*mv.x + mv.y*mv.y + mv.z*mv.z + mv.w*mv.w;
        a.z = sv.x*g0s.x + sv.y*g0s.y + sv.z*g0s.z + sv.w*g0s.w
            + mv.x*g0m.x + mv.y*g0m.y + mv.z*g0m.z + mv.w*g0m.w;
        a.w = sv.x*g1s.x + sv.y*g1s.y + sv.z*g1s.z + sv.w*g1s.w
            + mv.x*g1m.x + mv.y*g1m.y + mv.z*g1m.z + mv.w*g1m.w;
        acc[r] = warp_reduce4(a);
    }

    const int wid = t >> 5, lid = t & 31;
    if (lid == 0) {
#pragma unroll
        for (int r = 0; r < ROWS_PER_BLOCK; r++) sh[r][wid] = acc[r];
    }
    __syncthreads();

    // Warps 0..3 finalize one row each (6 partials -> scalar w0)
    if (wid < ROWS_PER_BLOCK) {
        float4 a = (lid < NWARPS_MAIN) ? sh[wid][lid]
                                       : make_float4(0.f, 0.f, 0.f, 0.f);
#pragma unroll
        for (int o = 4; o > 0; o >>= 1) {
            a.x += __shfl_down_sync(0xffffffffu, a.x, o);
            a.y += __shfl_down_sync(0xffffffffu, a.y, o);
            a.z += __shfl_down_sync(0xffffffffu, a.z, o);
            a.w += __shfl_down_sync(0xffffffffu, a.w, o);
        }
        if (lid == 0) {
            const float inv_n = 1.0f / (float)D_FULL;
            float mean = a.x * inv_n;
            float var  = fmaf(-mean, mean, a.y * inv_n);
            float rstd = rsqrtf(var + LN_EPS);
            float l0 = fmaf(rstd, a.z - mean * g_row_const[0], g_row_const[2]);
            float l1 = fmaf(rstd, a.w - mean * g_row_const[1], g_row_const[3]);
            sh_w0[wid] = 1.0f / (1.0f + __expf(l1 - l0));
        }
    }
    __syncthreads();

#pragma unroll
    for (int r = 0; r < ROWS_PER_BLOCK; r++) {
        float w0 = sh_w0[r];
        float w1 = 1.0f - w0;
        float4 o;
        o.x = fmaf(w0, s[r].x, w1 * m[r].x);
        o.y = fmaf(w0, s[r].y, w1 * m[r].y);
        o.z = fmaf(w0, s[r].z, w1 * m[r].z);
        o.w = fmaf(w0, s[r].w, w1 * m[r].w);
        stcs4(op + r * V_HALF, o);
    }
}

// ---------------------------------------------------------------------------
// Launch: prologue, then main with programmatic stream serialization (PDL)
// so the main grid launches while the prologue is still running.
// ---------------------------------------------------------------------------
extern "C" void kernel_launch(void* const* d_in, const int* in_sizes, int n_in,
                              void* d_out, int out_size) {
    const float* seq    = (const float*)d_in[0];
    const float* msa    = (const float*)d_in[1];
    const float* gamma  = (const float*)d_in[2];
    const float* beta   = (const float*)d_in[3];
    const float* gate_w = (const float*)d_in[4];
    const float* gate_b = (const float*)d_in[5];
    float* out = (float*)d_out;

    int rows   = in_sizes[0] / D_HALF;          // B*S = 16384
    int blocks = rows / ROWS_PER_BLOCK;         // 4096

    gate_const_kernel<<<1, NT_PRE>>>(gamma, beta, gate_w, gate_b);

    cudaLaunchConfig_t cfg = {};
    cfg.gridDim  = dim3(blocks, 1, 1);
    cfg.blockDim = dim3(NT_MAIN, 1, 1);
    cfg.dynamicSmemBytes = 0;
    cfg.stream = 0;
    cudaLaunchAttribute attrs[1];
    attrs[0].id = cudaLaunchAttributeProgrammaticStreamSerialization;
    attrs[0].val.programmaticStreamSerializationAllowed = 1;
    cfg.attrs = attrs;
    cfg.numAttrs = 1;

    const float4* seq4 = (const float4*)seq;
    const float4* msa4 = (const float4*)msa;
    float4* out4 = (float4*)out;
    cudaLaunchKernelEx(&cfg, attention_fusion_kernel, seq4, msa4, out4);
}